// round 9
// baseline (speedup 1.0000x reference)
#include <cuda_runtime.h>

// Depth-to-space k=3 (CRD): out[b, 3i+r, 3j+s] = in[b, 3r+s, i, j]
//   in : (32, 9, 512, 512) fp32   out: (32, 1, 1536, 1536) fp32
//
// R8 -> R9: persistent blocks, double-buffered smem, software pipeline.
// Per iteration (row n resident in buf[cur]):
//   1. __syncthreads()                    (buf[cur^1] stores from n-1 done)
//   2. issue 18 coalesced LDGs row n+1 -> regs      (no consumer yet)
//   3. STG row n: coalesced float4 from buf[cur]    (covers LDG latency)
//   4. STS scatter regs -> buf[cur^1]     (stride-3, conflict-free)
// Every block overlaps its own loads with its own stores -> continuous DRAM
// request stream instead of load/store phase bursts.
//
// 256 thr, 2 x 18KB smem -> 6 blocks/SM (216KB, 48 warps). Grid = 148*6.

#define THREADS 256
#define NROWS   16384          // 32 batches * 512 input rows
#define GRID    (148 * 6)

__device__ __forceinline__ void store_row(const float* __restrict__ buf,
                                          float* __restrict__ out,
                                          int row, int tid)
{
    const int i = row & 511;
    const int b = row >> 9;
    const float4* rv = reinterpret_cast<const float4*>(buf);
    float4* op = reinterpret_cast<float4*>(
        out + (size_t)(b * 1536 + 3 * i) * 1536);
    #pragma unroll
    for (int l = 0; l < 4; ++l)
        __stcs(&op[tid + l * THREADS], rv[tid + l * THREADS]);
    if (tid < 128)
        __stcs(&op[tid + 1024], rv[tid + 1024]);
}

__global__ __launch_bounds__(THREADS) void d2s_k3_pipe_kernel(
    const float* __restrict__ in, float* __restrict__ out)
{
    __shared__ float buf[2][4608];   // 2 x 18KB

    const int tid = threadIdx.x;
    int row = blockIdx.x;

    // prologue: load + scatter first row into buf[0]
    {
        const int i = row & 511, b = row >> 9;
        const float* ip = in + (size_t)b * 9 * 262144 + (size_t)i * 512;
        #pragma unroll
        for (int l = 0; l < 18; ++l) {
            const int t = tid + l * THREADS;
            const int c = t >> 9, col = t & 511;
            const int r = c / 3, s = c - 3 * r;
            buf[0][r * 1536 + 3 * col + s] = __ldcs(ip + c * 262144 + col);
        }
    }

    int cur = 0;
    for (;;) {
        const int nextrow = row + GRID;
        __syncthreads();                      // prior stores on buf[cur^1] done
        if (nextrow < NROWS) {
            // (2) issue next-row loads first — 18 independent LDGs in flight
            float v[18];
            const int i2 = nextrow & 511, b2 = nextrow >> 9;
            const float* ip2 = in + (size_t)b2 * 9 * 262144 + (size_t)i2 * 512;
            #pragma unroll
            for (int l = 0; l < 18; ++l) {
                const int t = tid + l * THREADS;
                v[l] = __ldcs(ip2 + (t >> 9) * 262144 + (t & 511));
            }
            // (3) store current row — overlaps the LDG latency above
            store_row(buf[cur], out, row, tid);
            // (4) scatter next row (consumes LDG results)
            #pragma unroll
            for (int l = 0; l < 18; ++l) {
                const int t = tid + l * THREADS;
                const int c = t >> 9, col = t & 511;
                const int r = c / 3, s = c - 3 * r;
                buf[cur ^ 1][r * 1536 + 3 * col + s] = v[l];
            }
            cur ^= 1;
            row = nextrow;
        } else {
            store_row(buf[cur], out, row, tid);   // epilogue
            break;
        }
    }
}

extern "C" void kernel_launch(void* const* d_in, const int* in_sizes, int n_in,
                              void* d_out, int out_size)
{
    const float* in  = (const float*)d_in[0];
    float*       out = (float*)d_out;

    d2s_k3_pipe_kernel<<<GRID, THREADS>>>(in, out);
}

// round 10
// speedup vs baseline: 1.1183x; 1.1183x over previous
#include <cuda_runtime.h>

// Depth-to-space k=3 (CRD): out[b, 3i+r, 3j+s] = in[b, 3r+s, i, j]
//   in : (32, 9, 512, 512) fp32   out: (32, 1, 1536, 1536) fp32
//
// R8 -> R10: one block per INPUT ROW PAIR (b, i0=2q) -> 6 output rows.
//   Reads : 9 chunks of 4KB contiguous (rows i0,i0+1 adjacent per channel)
//   Writes: 36KB contiguous (output rows 3*i0 .. 3*i0+5)
// Doubling burst granularity halves DRAM page activations per byte and
// lengthens same-direction streaks (less R/W turnaround) vs R8's 2KB reads.
//
// 512 thr, 36KB smem -> 4 blocks/SM = 64 warps (full occ), 18 LDGs/thread MLP.
// Scatter stride-3 words (gcd(3,32)=1) -> bank-conflict-free. Stores float4.

#define THREADS 512
#define SM_FLOATS 9216         // 6 rows * 1536 = 36KB

__global__ __launch_bounds__(THREADS) void d2s_k3_rowpair_kernel(
    const float* __restrict__ in, float* __restrict__ out)
{
    __shared__ float rows[SM_FLOATS];

    const int tid = threadIdx.x;
    const int bq  = blockIdx.x;        // b*256 + q
    const int q   = bq & 255;          // row-pair index
    const int b   = bq >> 8;
    const int i0  = q * 2;             // first input row of the pair

    // base of (batch b, row i0, channel 0); channel step 262144 floats,
    // each channel chunk = rows i0,i0+1 = 1024 contiguous floats (4KB)
    const float* ip = in + (size_t)b * 9 * 262144 + (size_t)i0 * 512;

    // 18 fully-coalesced independent streaming loads per thread
    #pragma unroll
    for (int l = 0; l < 18; ++l) {
        const int t   = tid + l * THREADS;   // 0..9215
        const int c   = t >> 10;             // channel 0..8
        const int rem = t & 1023;            // d*512 + j within the 4KB chunk
        float v = __ldcs(ip + c * 262144 + rem);
        const int d   = rem >> 9;            // row within pair (0/1)
        const int j   = rem & 511;           // input column
        const int r   = c / 3;
        const int s   = c - 3 * r;
        // output row within block = 3d + r
        rows[(3 * d + r) * 1536 + 3 * j + s] = v;   // conflict-free scatter
    }

    __syncthreads();

    // 36KB contiguous output: rows 3*i0 .. 3*i0+5 of batch b
    const float4* rv = reinterpret_cast<const float4*>(rows);
    float4* op = reinterpret_cast<float4*>(
        out + (size_t)(b * 1536 + 3 * i0) * 1536);

    #pragma unroll
    for (int l = 0; l < 4; ++l)
        __stcs(&op[tid + l * THREADS], rv[tid + l * THREADS]);
    if (tid < 256)
        __stcs(&op[tid + 2048], rv[tid + 2048]);
}

extern "C" void kernel_launch(void* const* d_in, const int* in_sizes, int n_in,
                              void* d_out, int out_size)
{
    const float* in  = (const float*)d_in[0];
    float*       out = (float*)d_out;

    d2s_k3_rowpair_kernel<<<32 * 256, THREADS>>>(in, out);
}

// round 11
// speedup vs baseline: 1.1187x; 1.0003x over previous
#include <cuda_runtime.h>
#include <cstdint>

// Depth-to-space k=3 (CRD): out[b, 3i+r, 3j+s] = in[b, 3r+s, i, j]
//   in : (32, 9, 512, 512) fp32   out: (32, 1, 1536, 1536) fp32
//
// R8 -> R11: identical load/scatter (18 independent coalesced LDG.32 per
// thread -> stride-3 conflict-free STS), but the store phase is ONE TMA bulk
// copy (cp.async.bulk smem->gmem, 18KB contiguous) instead of 36 STG.128
// waves. Removes all store wavefronts from L1tex and emits the output row
// as a single continuous DRAM write burst (longer same-direction streaks ->
// less R/W turnaround). wait_group.read only holds until smem reads finish.
//
// 256 thr, 18KB smem -> 8 blocks/SM (full 2048 threads). Grid = 32*512.

#define THREADS 256
#define ROW3 4608            // 3 * 1536 floats = 18KB
#define ROW3_BYTES 18432

__global__ __launch_bounds__(THREADS) void d2s_k3_tma_kernel(
    const float* __restrict__ in, float* __restrict__ out)
{
    __shared__ __align__(128) float rows[ROW3];

    const int tid = threadIdx.x;
    const int bi  = blockIdx.x;        // b*512 + i
    const int i   = bi & 511;
    const int b   = bi >> 9;

    const float* ip = in + (size_t)b * 9 * 262144 + (size_t)i * 512;

    // 18 fully-coalesced independent streaming loads, conflict-free scatter
    #pragma unroll
    for (int l = 0; l < 18; ++l) {
        const int t   = tid + l * THREADS;   // 0..4607
        const int c   = t >> 9;              // channel 0..8 (const per l)
        const int col = t & 511;
        float v = __ldcs(ip + c * 262144 + col);
        const int r = c / 3;
        const int s = c - 3 * r;
        rows[r * 1536 + 3 * col + s] = v;
    }

    __syncthreads();

    if (tid == 0) {
        // make generic-proxy STS visible to the async (TMA) proxy
        asm volatile("fence.proxy.async.shared::cta;" ::: "memory");

        uint32_t saddr;
        asm("{ .reg .u64 t; cvta.to.shared.u64 t, %1; cvt.u32.u64 %0, t; }"
            : "=r"(saddr) : "l"(rows));

        float* dst = out + (size_t)(b * 1536 + 3 * i) * 1536;  // 18KB, 16B-aligned

        asm volatile(
            "cp.async.bulk.global.shared::cta.bulk_group [%0], [%1], %2;"
            :: "l"(dst), "r"(saddr), "r"(ROW3_BYTES) : "memory");
        asm volatile("cp.async.bulk.commit_group;" ::: "memory");
        // wait only until the smem source has been read (block may then exit)
        asm volatile("cp.async.bulk.wait_group.read 0;" ::: "memory");
    }
}

extern "C" void kernel_launch(void* const* d_in, const int* in_sizes, int n_in,
                              void* d_out, int out_size)
{
    const float* in  = (const float*)d_in[0];
    float*       out = (float*)d_out;

    d2s_k3_tma_kernel<<<32 * 512, THREADS>>>(in, out);
}